// round 14
// baseline (speedup 1.0000x reference)
#include <cuda_runtime.h>
#include <math.h>
#include <float.h>

#define NN 50000
#define EE 800000
#define E2 (EE + NN)      // edges + self loops = 850000
#define ETEST 100000
#define ETOT 200000

// ---------------- scratch (device globals) ----------------------------------
__device__ __align__(16) float g_h1[NN * 64];
__device__ __align__(16) float g_as1[NN * 8];
__device__ __align__(16) float g_ad1[NN * 8];
__device__ __align__(16) float g_z1[NN * 64];

__device__ __align__(16) float g_h2[NN * 64];
__device__ __align__(16) float g_as2[NN];
__device__ __align__(16) float g_ad2[NN];
__device__ __align__(16) float g_z2[NN * 64];

__device__ __align__(16) int g_deg[NN];     // zero at load; scan re-zeroes
__device__ __align__(16) int g_off[NN + 1];
__device__ __align__(16) int g_epos[E2];
__device__ __align__(16) int g_csr_src[E2];

// ---------------- helpers --------------------------------------------------
__device__ __forceinline__ float lrelu(float x) { return x > 0.0f ? x : 0.2f * x; }

__device__ __forceinline__ float dot4(float4 a, float4 b) {
    return fmaf(a.x, b.x, fmaf(a.y, b.y, fmaf(a.z, b.z, a.w * b.w)));
}

// ---------------- CSR build -------------------------------------------------
// count + record per-edge intra-bucket position (makes scatter atomic-free)
__global__ __launch_bounds__(256) void count_deg(const int* __restrict__ ei) {
    int e0 = (blockIdx.x * blockDim.x + threadIdx.x) * 4;
#pragma unroll
    for (int j = 0; j < 4; j++) {
        int e = e0 + j;
        if (e < E2) {
            int d = (e < EE) ? ei[EE + e] : (e - EE);
            g_epos[e] = atomicAdd(&g_deg[d], 1);
        }
    }
}

// single-block scan with coalesced smem staging; re-zeroes g_deg for next run
__global__ void scan_kernel() {
    extern __shared__ int sdeg[];           // NN ints (200 KB)
    __shared__ int ssum[1024];
    const int CH = (NN + 1023) / 1024;      // 49
    int t = threadIdx.x;
    for (int i = t; i < NN; i += 1024) {
        sdeg[i] = g_deg[i];
        g_deg[i] = 0;                       // invariant: g_deg zero on entry
    }
    __syncthreads();
    int base = t * CH;
    int s = 0;
    for (int i = 0; i < CH; i++) {
        int idx = base + i;
        if (idx < NN) s += sdeg[idx];
    }
    ssum[t] = s;
    __syncthreads();
    for (int off = 1; off < 1024; off <<= 1) {
        int v = (t >= off) ? ssum[t - off] : 0;
        __syncthreads();
        ssum[t] += v;
        __syncthreads();
    }
    int run = (t == 0) ? 0 : ssum[t - 1];
    for (int i = 0; i < CH; i++) {
        int idx = base + i;
        if (idx < NN) {
            g_off[idx] = run;
            run += sdeg[idx];
        }
    }
    if (t == 1023) g_off[NN] = E2;
}

// atomic-free scatter: position = off[d] + epos[e]
__global__ __launch_bounds__(256) void scatter_kernel(const int* __restrict__ ei) {
    int e0 = (blockIdx.x * blockDim.x + threadIdx.x) * 4;
#pragma unroll
    for (int j = 0; j < 4; j++) {
        int e = e0 + j;
        if (e < E2) {
            int s, d;
            if (e < EE) { s = ei[e]; d = ei[EE + e]; }
            else        { s = e - EE; d = s; }
            g_csr_src[g_off[d] + g_epos[e]] = s;
        }
    }
}

// ---------------- fused GEMM + attention scores ------------------------------
// Block tile 128 rows x 64 cols, 256 threads, thread tile 8x4.
// 12 LDS.128 feed 128 FMA per 4-k per thread (1.5 smem-B/FMA).
template <int K, int LAYER>
__global__ __launch_bounds__(256) void gemm_att(
        const float* __restrict__ Xin, const float* __restrict__ W,
        const float* __restrict__ att_s, const float* __restrict__ att_d) {
    __shared__ float xs[128 * 64];   // 32 KB
    __shared__ float ws[64 * 64];    // 16 KB
    const float* X = (LAYER == 1) ? Xin : g_z1;
    float* H = (LAYER == 1) ? g_h1 : g_h2;

    int tid = threadIdx.x;
    int cg = tid & 15;        // col group (4 cols)
    int rg = tid >> 4;        // row group (8 rows)
    int rowBase = blockIdx.x * 128;

    float acc[8][4];
#pragma unroll
    for (int a = 0; a < 8; a++)
#pragma unroll
        for (int b = 0; b < 4; b++) acc[a][b] = 0.f;

    const float4* X4 = reinterpret_cast<const float4*>(X);
    const float4* W4 = reinterpret_cast<const float4*>(W);

    for (int kc = 0; kc < K; kc += 64) {
        // stage xs: 128 rows x 64 k = 2048 float4
#pragma unroll
        for (int i = tid; i < 2048; i += 256) {
            int row = i >> 4, q = i & 15;
            float4 v = (rowBase + row < NN)
                ? X4[(size_t)(rowBase + row) * (K / 4) + (kc / 4) + q]
                : make_float4(0.f, 0.f, 0.f, 0.f);
            *reinterpret_cast<float4*>(&xs[row * 64 + q * 4]) = v;
        }
        // stage ws: 64 k x 64 cols = 1024 float4
#pragma unroll
        for (int i = tid; i < 1024; i += 256) {
            *reinterpret_cast<float4*>(&ws[i * 4]) = W4[kc * 16 + i];
        }
        __syncthreads();

#pragma unroll 4
        for (int k0 = 0; k0 < 64; k0 += 4) {
            float4 wv[4];
#pragma unroll
            for (int j = 0; j < 4; j++)
                wv[j] = *reinterpret_cast<const float4*>(&ws[(k0 + j) * 64 + cg * 4]);
#pragma unroll
            for (int r = 0; r < 8; r++) {
                float4 xv = *reinterpret_cast<const float4*>(&xs[(rg * 8 + r) * 64 + k0]);
                acc[r][0] = fmaf(xv.x, wv[0].x, acc[r][0]);
                acc[r][1] = fmaf(xv.x, wv[0].y, acc[r][1]);
                acc[r][2] = fmaf(xv.x, wv[0].z, acc[r][2]);
                acc[r][3] = fmaf(xv.x, wv[0].w, acc[r][3]);
                acc[r][0] = fmaf(xv.y, wv[1].x, acc[r][0]);
                acc[r][1] = fmaf(xv.y, wv[1].y, acc[r][1]);
                acc[r][2] = fmaf(xv.y, wv[1].z, acc[r][2]);
                acc[r][3] = fmaf(xv.y, wv[1].w, acc[r][3]);
                acc[r][0] = fmaf(xv.z, wv[2].x, acc[r][0]);
                acc[r][1] = fmaf(xv.z, wv[2].y, acc[r][1]);
                acc[r][2] = fmaf(xv.z, wv[2].z, acc[r][2]);
                acc[r][3] = fmaf(xv.z, wv[2].w, acc[r][3]);
                acc[r][0] = fmaf(xv.w, wv[3].x, acc[r][0]);
                acc[r][1] = fmaf(xv.w, wv[3].y, acc[r][1]);
                acc[r][2] = fmaf(xv.w, wv[3].z, acc[r][2]);
                acc[r][3] = fmaf(xv.w, wv[3].w, acc[r][3]);
            }
        }
        __syncthreads();
    }

    float aw_s[4], aw_d[4];
#pragma unroll
    for (int cc = 0; cc < 4; cc++) {
        aw_s[cc] = __ldg(&att_s[cg * 4 + cc]);
        aw_d[cc] = __ldg(&att_d[cg * 4 + cc]);
    }

#pragma unroll
    for (int rr = 0; rr < 8; rr++) {
        int row = rowBase + rg * 8 + rr;
        bool ok = row < NN;
        if (ok) {
            float4 hv = make_float4(acc[rr][0], acc[rr][1], acc[rr][2], acc[rr][3]);
            *reinterpret_cast<float4*>(&H[(size_t)row * 64 + cg * 4]) = hv;
        }
        float ps = 0.f, pd = 0.f;
#pragma unroll
        for (int cc = 0; cc < 4; cc++) {
            ps = fmaf(acc[rr][cc], aw_s[cc], ps);
            pd = fmaf(acc[rr][cc], aw_d[cc], pd);
        }
        if (LAYER == 1) {
            ps += __shfl_xor_sync(0xffffffffu, ps, 1);
            pd += __shfl_xor_sync(0xffffffffu, pd, 1);
            if (!(cg & 1) && ok) {
                g_as1[row * 8 + (cg >> 1)] = ps;
                g_ad1[row * 8 + (cg >> 1)] = pd;
            }
        } else {
            ps += __shfl_xor_sync(0xffffffffu, ps, 1);
            pd += __shfl_xor_sync(0xffffffffu, pd, 1);
            ps += __shfl_xor_sync(0xffffffffu, ps, 2);
            pd += __shfl_xor_sync(0xffffffffu, pd, 2);
            ps += __shfl_xor_sync(0xffffffffu, ps, 4);
            pd += __shfl_xor_sync(0xffffffffu, pd, 4);
            ps += __shfl_xor_sync(0xffffffffu, ps, 8);
            pd += __shfl_xor_sync(0xffffffffu, pd, 8);
            if (cg == 0 && ok) {
                g_as2[row] = ps;
                g_ad2[row] = pd;
            }
        }
    }
}

// ---------------- layer-1 aggregation: warp/dst, float2 lanes, unroll 8 ------
__global__ __launch_bounds__(256) void agg1_kernel(const float* __restrict__ bias) {
    int warp = (blockIdx.x * blockDim.x + threadIdx.x) >> 5;
    int lane = threadIdx.x & 31;
    if (warp >= NN) return;
    int d = warp;
    int beg = g_off[d], end = g_off[d + 1];

    int laneH = lane & 7;
    float adh = g_ad1[d * 8 + laneH];
    int hh = lane >> 2;  // head of channels 2*lane, 2*lane+1

    const float2* H2 = reinterpret_cast<const float2*>(g_h1);
    float2 numA = make_float2(0.f, 0.f), numB = make_float2(0.f, 0.f);
    float denA = 0.f, denB = 0.f;
    int i = beg;
    for (; i + 7 < end; i += 8) {
        int sIdx[8];
#pragma unroll
        for (int j = 0; j < 8; j++) sIdx[j] = g_csr_src[i + j];
        float aV[8]; float2 vV[8];
#pragma unroll
        for (int j = 0; j < 8; j++) {
            aV[j] = g_as1[sIdx[j] * 8 + laneH];
            vV[j] = H2[sIdx[j] * 32 + lane];
        }
#pragma unroll
        for (int j = 0; j < 8; j++) aV[j] = __expf(lrelu(aV[j] + adh));
#pragma unroll
        for (int j = 0; j < 8; j++) {
            float e = __shfl_sync(0xffffffffu, aV[j], hh);
            if (j & 1) { numB.x = fmaf(e, vV[j].x, numB.x); numB.y = fmaf(e, vV[j].y, numB.y); denB += e; }
            else       { numA.x = fmaf(e, vV[j].x, numA.x); numA.y = fmaf(e, vV[j].y, numA.y); denA += e; }
        }
    }
    for (; i < end; i++) {
        int s0 = g_csr_src[i];
        float a0 = g_as1[s0 * 8 + laneH];
        float2 v0 = H2[s0 * 32 + lane];
        float x0 = __expf(lrelu(a0 + adh));
        float e0 = __shfl_sync(0xffffffffu, x0, hh);
        numA.x = fmaf(e0, v0.x, numA.x); numA.y = fmaf(e0, v0.y, numA.y); denA += e0;
    }
    float inv = 1.0f / fmaxf(denA + denB, 1e-16f);
    const float2* B2 = reinterpret_cast<const float2*>(bias);
    float2 bv = B2[lane];
    float o0 = (numA.x + numB.x) * inv + bv.x;
    float o1 = (numA.y + numB.y) * inv + bv.y;
    float2 ov;
    ov.x = o0 > 0.f ? o0 : expm1f(o0);   // ELU
    ov.y = o1 > 0.f ? o1 : expm1f(o1);
    reinterpret_cast<float2*>(g_z1)[d * 32 + lane] = ov;
}

// ---------------- layer-2 aggregation: warp/dst, float2 lanes, unroll 8 ------
__global__ __launch_bounds__(256) void agg2_kernel(const float* __restrict__ bias) {
    int warp = (blockIdx.x * blockDim.x + threadIdx.x) >> 5;
    int lane = threadIdx.x & 31;
    if (warp >= NN) return;
    int d = warp;
    int beg = g_off[d], end = g_off[d + 1];

    float ad = g_ad2[d];
    const float2* H2 = reinterpret_cast<const float2*>(g_h2);
    float2 numA = make_float2(0.f, 0.f), numB = make_float2(0.f, 0.f);
    float denA = 0.f, denB = 0.f;
    int i = beg;
    for (; i + 7 < end; i += 8) {
        int sIdx[8];
#pragma unroll
        for (int j = 0; j < 8; j++) sIdx[j] = g_csr_src[i + j];
        float aV[8]; float2 vV[8];
#pragma unroll
        for (int j = 0; j < 8; j++) {
            aV[j] = g_as2[sIdx[j]];
            vV[j] = H2[sIdx[j] * 32 + lane];
        }
#pragma unroll
        for (int j = 0; j < 8; j++) {
            float e = __expf(lrelu(aV[j] + ad));
            if (j & 1) { numB.x = fmaf(e, vV[j].x, numB.x); numB.y = fmaf(e, vV[j].y, numB.y); denB += e; }
            else       { numA.x = fmaf(e, vV[j].x, numA.x); numA.y = fmaf(e, vV[j].y, numA.y); denA += e; }
        }
    }
    for (; i < end; i++) {
        int s0 = g_csr_src[i];
        float2 v0 = H2[s0 * 32 + lane];
        float e0 = __expf(lrelu(g_as2[s0] + ad));
        numA.x = fmaf(e0, v0.x, numA.x); numA.y = fmaf(e0, v0.y, numA.y); denA += e0;
    }
    float inv = 1.0f / fmaxf(denA + denB, 1e-16f);
    const float2* B2 = reinterpret_cast<const float2*>(bias);
    float2 bv = B2[lane];
    float2 ov;
    ov.x = (numA.x + numB.x) * inv + bv.x;
    ov.y = (numA.y + numB.y) * inv + bv.y;
    reinterpret_cast<float2*>(g_z2)[d * 32 + lane] = ov;
}

// ---------------- link prediction logits: 16 threads per edge ----------------
__global__ __launch_bounds__(256) void logits_kernel(const int* __restrict__ pos,
                                                     const int* __restrict__ neg,
                                                     float* __restrict__ out) {
    int t = blockIdx.x * blockDim.x + threadIdx.x;
    int edge = t >> 4, sub = t & 15;
    if (edge >= ETOT) return;
    int s, d;
    if (edge < ETEST) { s = pos[edge]; d = pos[ETEST + edge]; }
    else              { s = neg[edge - ETEST]; d = neg[ETEST + (edge - ETEST)]; }
    const float4* Z4 = reinterpret_cast<const float4*>(g_z2);
    float4 a = Z4[(size_t)s * 16 + sub];
    float4 b = Z4[(size_t)d * 16 + sub];
    float p = dot4(a, b);
    p += __shfl_xor_sync(0xffffffffu, p, 1);
    p += __shfl_xor_sync(0xffffffffu, p, 2);
    p += __shfl_xor_sync(0xffffffffu, p, 4);
    p += __shfl_xor_sync(0xffffffffu, p, 8);
    if (sub == 0) out[edge] = p;
}

// ---------------- launch ----------------------------------------------------
extern "C" void kernel_launch(void* const* d_in, const int* in_sizes, int n_in,
                              void* d_out, int out_size) {
    const float* x    = (const float*)d_in[0];
    const int*   ei   = (const int*)d_in[1];
    const int*   pos  = (const int*)d_in[2];
    const int*   neg  = (const int*)d_in[3];
    const float* W1   = (const float*)d_in[4];
    const float* as1  = (const float*)d_in[5];
    const float* ad1  = (const float*)d_in[6];
    const float* b1   = (const float*)d_in[7];
    const float* W2   = (const float*)d_in[8];
    const float* as2  = (const float*)d_in[9];
    const float* ad2  = (const float*)d_in[10];
    const float* b2   = (const float*)d_in[11];
    float* out = (float*)d_out;

    const int TB = 256;
    const int E4 = (E2 + 3) / 4;
    const int SCAN_SMEM = NN * (int)sizeof(int);   // 200 KB dynamic smem
    cudaFuncSetAttribute(scan_kernel, cudaFuncAttributeMaxDynamicSharedMemorySize,
                         SCAN_SMEM);

    // CSR build (g_deg zeroed at load / by previous run's scan)
    count_deg<<<(E4 + TB - 1) / TB, TB>>>(ei);
    scan_kernel<<<1, 1024, SCAN_SMEM>>>();
    scatter_kernel<<<(E4 + TB - 1) / TB, TB>>>(ei);
    // layer 1 (GEMM + att fused), 128-row tiles
    gemm_att<128, 1><<<(NN + 127) / 128, TB>>>(x, W1, as1, ad1);
    agg1_kernel<<<(NN * 32 + TB - 1) / TB, TB>>>(b1);
    // layer 2
    gemm_att<64, 2><<<(NN + 127) / 128, TB>>>(nullptr, W2, as2, ad2);
    agg2_kernel<<<(NN * 32 + TB - 1) / TB, TB>>>(b2);
    // logits (16 threads per test edge)
    logits_kernel<<<(ETOT * 16 + TB - 1) / TB, TB>>>(pos, neg, out);
}

// round 15
// speedup vs baseline: 1.4754x; 1.4754x over previous
#include <cuda_runtime.h>
#include <math.h>
#include <float.h>

#define NN 50000
#define EE 800000
#define E2 (EE + NN)      // edges + self loops = 850000
#define ETEST 100000
#define ETOT 200000

// ---------------- scratch (device globals) ----------------------------------
__device__ __align__(16) float g_h1[NN * 64];
__device__ __align__(16) float g_as1[NN * 8];
__device__ __align__(16) float g_ad1[NN * 8];
__device__ __align__(16) float g_z1[NN * 64];

__device__ __align__(16) float g_h2[NN * 64];
__device__ __align__(16) float g_as2[NN];
__device__ __align__(16) float g_ad2[NN];
__device__ __align__(16) float g_z2[NN * 64];

__device__ __align__(16) int g_deg[NN];     // zero at load; scan re-zeroes
__device__ __align__(16) int g_off[NN + 1];
__device__ __align__(16) int g_epos[E2];
__device__ __align__(16) int g_csr_src[E2];

// ---------------- helpers --------------------------------------------------
__device__ __forceinline__ float lrelu(float x) { return x > 0.0f ? x : 0.2f * x; }

__device__ __forceinline__ float dot4(float4 a, float4 b) {
    return fmaf(a.x, b.x, fmaf(a.y, b.y, fmaf(a.z, b.z, a.w * b.w)));
}

// ---------------- CSR build -------------------------------------------------
// count + record per-edge intra-bucket position (makes scatter atomic-free)
__global__ __launch_bounds__(256) void count_deg(const int* __restrict__ ei) {
    int e0 = (blockIdx.x * blockDim.x + threadIdx.x) * 4;
#pragma unroll
    for (int j = 0; j < 4; j++) {
        int e = e0 + j;
        if (e < E2) {
            int d = (e < EE) ? ei[EE + e] : (e - EE);
            g_epos[e] = atomicAdd(&g_deg[d], 1);
        }
    }
}

// single-block scan with coalesced smem staging; re-zeroes g_deg for next run
__global__ void scan_kernel() {
    extern __shared__ int sdeg[];           // NN ints (200 KB)
    __shared__ int ssum[1024];
    const int CH = (NN + 1023) / 1024;      // 49
    int t = threadIdx.x;
    for (int i = t; i < NN; i += 1024) {
        sdeg[i] = g_deg[i];
        g_deg[i] = 0;                       // invariant: g_deg zero on entry
    }
    __syncthreads();
    int base = t * CH;
    int s = 0;
    for (int i = 0; i < CH; i++) {
        int idx = base + i;
        if (idx < NN) s += sdeg[idx];
    }
    ssum[t] = s;
    __syncthreads();
    for (int off = 1; off < 1024; off <<= 1) {
        int v = (t >= off) ? ssum[t - off] : 0;
        __syncthreads();
        ssum[t] += v;
        __syncthreads();
    }
    int run = (t == 0) ? 0 : ssum[t - 1];
    for (int i = 0; i < CH; i++) {
        int idx = base + i;
        if (idx < NN) {
            g_off[idx] = run;
            run += sdeg[idx];
        }
    }
    if (t == 1023) g_off[NN] = E2;
}

// atomic-free scatter: position = off[d] + epos[e]
__global__ __launch_bounds__(256) void scatter_kernel(const int* __restrict__ ei) {
    int e0 = (blockIdx.x * blockDim.x + threadIdx.x) * 4;
#pragma unroll
    for (int j = 0; j < 4; j++) {
        int e = e0 + j;
        if (e < E2) {
            int s, d;
            if (e < EE) { s = ei[e]; d = ei[EE + e]; }
            else        { s = e - EE; d = s; }
            g_csr_src[g_off[d] + g_epos[e]] = s;
        }
    }
}

// ---------------- fused GEMM + attention scores ------------------------------
// Block tile 64x64, 256 threads, thread tile 4x4, k stepped by 4 with
// both operands as LDS.128 — the measured-best configuration.
template <int K, int LAYER>
__global__ __launch_bounds__(256) void gemm_att(
        const float* __restrict__ Xin, const float* __restrict__ W,
        const float* __restrict__ att_s, const float* __restrict__ att_d) {
    __shared__ float xs[64 * 64];
    __shared__ float ws[64 * 64];
    const float* X = (LAYER == 1) ? Xin : g_z1;
    float* H = (LAYER == 1) ? g_h1 : g_h2;

    int tid = threadIdx.x;
    int cg = tid & 15;        // col group (4 cols)
    int rg = tid >> 4;        // row group (4 rows)
    int rowBase = blockIdx.x * 64;

    float acc[4][4];
#pragma unroll
    for (int a = 0; a < 4; a++)
#pragma unroll
        for (int b = 0; b < 4; b++) acc[a][b] = 0.f;

    const float4* X4 = reinterpret_cast<const float4*>(X);
    const float4* W4 = reinterpret_cast<const float4*>(W);

    for (int kc = 0; kc < K; kc += 64) {
#pragma unroll
        for (int i = tid; i < 1024; i += 256) {
            int row = i >> 4, q = i & 15;
            float4 v = (rowBase + row < NN)
                ? X4[(size_t)(rowBase + row) * (K / 4) + (kc / 4) + q]
                : make_float4(0.f, 0.f, 0.f, 0.f);
            *reinterpret_cast<float4*>(&xs[row * 64 + q * 4]) = v;
        }
#pragma unroll
        for (int i = tid; i < 1024; i += 256) {
            *reinterpret_cast<float4*>(&ws[i * 4]) = W4[kc * 16 + i];
        }
        __syncthreads();

#pragma unroll
        for (int k0 = 0; k0 < 64; k0 += 4) {
            float4 xv[4], wv[4];
#pragma unroll
            for (int r = 0; r < 4; r++)
                xv[r] = *reinterpret_cast<const float4*>(&xs[(rg * 4 + r) * 64 + k0]);
#pragma unroll
            for (int j = 0; j < 4; j++)
                wv[j] = *reinterpret_cast<const float4*>(&ws[(k0 + j) * 64 + cg * 4]);
#pragma unroll
            for (int r = 0; r < 4; r++) {
                acc[r][0] = fmaf(xv[r].x, wv[0].x, acc[r][0]);
                acc[r][1] = fmaf(xv[r].x, wv[0].y, acc[r][1]);
                acc[r][2] = fmaf(xv[r].x, wv[0].z, acc[r][2]);
                acc[r][3] = fmaf(xv[r].x, wv[0].w, acc[r][3]);
                acc[r][0] = fmaf(xv[r].y, wv[1].x, acc[r][0]);
                acc[r][1] = fmaf(xv[r].y, wv[1].y, acc[r][1]);
                acc[r][2] = fmaf(xv[r].y, wv[1].z, acc[r][2]);
                acc[r][3] = fmaf(xv[r].y, wv[1].w, acc[r][3]);
                acc[r][0] = fmaf(xv[r].z, wv[2].x, acc[r][0]);
                acc[r][1] = fmaf(xv[r].z, wv[2].y, acc[r][1]);
                acc[r][2] = fmaf(xv[r].z, wv[2].z, acc[r][2]);
                acc[r][3] = fmaf(xv[r].z, wv[2].w, acc[r][3]);
                acc[r][0] = fmaf(xv[r].w, wv[3].x, acc[r][0]);
                acc[r][1] = fmaf(xv[r].w, wv[3].y, acc[r][1]);
                acc[r][2] = fmaf(xv[r].w, wv[3].z, acc[r][2]);
                acc[r][3] = fmaf(xv[r].w, wv[3].w, acc[r][3]);
            }
        }
        __syncthreads();
    }

    float aw_s[4], aw_d[4];
#pragma unroll
    for (int cc = 0; cc < 4; cc++) {
        aw_s[cc] = __ldg(&att_s[cg * 4 + cc]);
        aw_d[cc] = __ldg(&att_d[cg * 4 + cc]);
    }

#pragma unroll
    for (int rr = 0; rr < 4; rr++) {
        int row = rowBase + rg * 4 + rr;
        bool ok = row < NN;
        if (ok) {
            float4 hv = make_float4(acc[rr][0], acc[rr][1], acc[rr][2], acc[rr][3]);
            *reinterpret_cast<float4*>(&H[(size_t)row * 64 + cg * 4]) = hv;
        }
        float ps = 0.f, pd = 0.f;
#pragma unroll
        for (int cc = 0; cc < 4; cc++) {
            ps = fmaf(acc[rr][cc], aw_s[cc], ps);
            pd = fmaf(acc[rr][cc], aw_d[cc], pd);
        }
        if (LAYER == 1) {
            ps += __shfl_xor_sync(0xffffffffu, ps, 1);
            pd += __shfl_xor_sync(0xffffffffu, pd, 1);
            if (!(cg & 1) && ok) {
                g_as1[row * 8 + (cg >> 1)] = ps;
                g_ad1[row * 8 + (cg >> 1)] = pd;
            }
        } else {
            ps += __shfl_xor_sync(0xffffffffu, ps, 1);
            pd += __shfl_xor_sync(0xffffffffu, pd, 1);
            ps += __shfl_xor_sync(0xffffffffu, ps, 2);
            pd += __shfl_xor_sync(0xffffffffu, pd, 2);
            ps += __shfl_xor_sync(0xffffffffu, ps, 4);
            pd += __shfl_xor_sync(0xffffffffu, pd, 4);
            ps += __shfl_xor_sync(0xffffffffu, ps, 8);
            pd += __shfl_xor_sync(0xffffffffu, pd, 8);
            if (cg == 0 && ok) {
                g_as2[row] = ps;
                g_ad2[row] = pd;
            }
        }
    }
}

// ---------------- layer-1 aggregation: warp/dst, float2 lanes, unroll 8 ------
__global__ __launch_bounds__(256) void agg1_kernel(const float* __restrict__ bias) {
    int warp = (blockIdx.x * blockDim.x + threadIdx.x) >> 5;
    int lane = threadIdx.x & 31;
    if (warp >= NN) return;
    int d = warp;
    int beg = g_off[d], end = g_off[d + 1];

    int laneH = lane & 7;
    float adh = g_ad1[d * 8 + laneH];
    int hh = lane >> 2;  // head of channels 2*lane, 2*lane+1

    const float2* H2 = reinterpret_cast<const float2*>(g_h1);
    float2 numA = make_float2(0.f, 0.f), numB = make_float2(0.f, 0.f);
    float denA = 0.f, denB = 0.f;
    int i = beg;
    for (; i + 7 < end; i += 8) {
        int sIdx[8];
#pragma unroll
        for (int j = 0; j < 8; j++) sIdx[j] = g_csr_src[i + j];
        float aV[8]; float2 vV[8];
#pragma unroll
        for (int j = 0; j < 8; j++) {
            aV[j] = g_as1[sIdx[j] * 8 + laneH];
            vV[j] = H2[sIdx[j] * 32 + lane];
        }
#pragma unroll
        for (int j = 0; j < 8; j++) aV[j] = __expf(lrelu(aV[j] + adh));
#pragma unroll
        for (int j = 0; j < 8; j++) {
            float e = __shfl_sync(0xffffffffu, aV[j], hh);
            if (j & 1) { numB.x = fmaf(e, vV[j].x, numB.x); numB.y = fmaf(e, vV[j].y, numB.y); denB += e; }
            else       { numA.x = fmaf(e, vV[j].x, numA.x); numA.y = fmaf(e, vV[j].y, numA.y); denA += e; }
        }
    }
    for (; i < end; i++) {
        int s0 = g_csr_src[i];
        float a0 = g_as1[s0 * 8 + laneH];
        float2 v0 = H2[s0 * 32 + lane];
        float x0 = __expf(lrelu(a0 + adh));
        float e0 = __shfl_sync(0xffffffffu, x0, hh);
        numA.x = fmaf(e0, v0.x, numA.x); numA.y = fmaf(e0, v0.y, numA.y); denA += e0;
    }
    float inv = 1.0f / fmaxf(denA + denB, 1e-16f);
    const float2* B2 = reinterpret_cast<const float2*>(bias);
    float2 bv = B2[lane];
    float o0 = (numA.x + numB.x) * inv + bv.x;
    float o1 = (numA.y + numB.y) * inv + bv.y;
    float2 ov;
    ov.x = o0 > 0.f ? o0 : expm1f(o0);   // ELU
    ov.y = o1 > 0.f ? o1 : expm1f(o1);
    reinterpret_cast<float2*>(g_z1)[d * 32 + lane] = ov;
}

// ---------------- layer-2 aggregation: warp/dst, float2 lanes, unroll 8 ------
__global__ __launch_bounds__(256) void agg2_kernel(const float* __restrict__ bias) {
    int warp = (blockIdx.x * blockDim.x + threadIdx.x) >> 5;
    int lane = threadIdx.x & 31;
    if (warp >= NN) return;
    int d = warp;
    int beg = g_off[d], end = g_off[d + 1];

    float ad = g_ad2[d];
    const float2* H2 = reinterpret_cast<const float2*>(g_h2);
    float2 numA = make_float2(0.f, 0.f), numB = make_float2(0.f, 0.f);
    float denA = 0.f, denB = 0.f;
    int i = beg;
    for (; i + 7 < end; i += 8) {
        int sIdx[8];
#pragma unroll
        for (int j = 0; j < 8; j++) sIdx[j] = g_csr_src[i + j];
        float aV[8]; float2 vV[8];
#pragma unroll
        for (int j = 0; j < 8; j++) {
            aV[j] = g_as2[sIdx[j]];
            vV[j] = H2[sIdx[j] * 32 + lane];
        }
#pragma unroll
        for (int j = 0; j < 8; j++) {
            float e = __expf(lrelu(aV[j] + ad));
            if (j & 1) { numB.x = fmaf(e, vV[j].x, numB.x); numB.y = fmaf(e, vV[j].y, numB.y); denB += e; }
            else       { numA.x = fmaf(e, vV[j].x, numA.x); numA.y = fmaf(e, vV[j].y, numA.y); denA += e; }
        }
    }
    for (; i < end; i++) {
        int s0 = g_csr_src[i];
        float2 v0 = H2[s0 * 32 + lane];
        float e0 = __expf(lrelu(g_as2[s0] + ad));
        numA.x = fmaf(e0, v0.x, numA.x); numA.y = fmaf(e0, v0.y, numA.y); denA += e0;
    }
    float inv = 1.0f / fmaxf(denA + denB, 1e-16f);
    const float2* B2 = reinterpret_cast<const float2*>(bias);
    float2 bv = B2[lane];
    float2 ov;
    ov.x = (numA.x + numB.x) * inv + bv.x;
    ov.y = (numA.y + numB.y) * inv + bv.y;
    reinterpret_cast<float2*>(g_z2)[d * 32 + lane] = ov;
}

// ---------------- link prediction logits: 16 threads per edge ----------------
__global__ __launch_bounds__(256) void logits_kernel(const int* __restrict__ pos,
                                                     const int* __restrict__ neg,
                                                     float* __restrict__ out) {
    int t = blockIdx.x * blockDim.x + threadIdx.x;
    int edge = t >> 4, sub = t & 15;
    if (edge >= ETOT) return;
    int s, d;
    if (edge < ETEST) { s = pos[edge]; d = pos[ETEST + edge]; }
    else              { s = neg[edge - ETEST]; d = neg[ETEST + (edge - ETEST)]; }
    const float4* Z4 = reinterpret_cast<const float4*>(g_z2);
    float4 a = Z4[(size_t)s * 16 + sub];
    float4 b = Z4[(size_t)d * 16 + sub];
    float p = dot4(a, b);
    p += __shfl_xor_sync(0xffffffffu, p, 1);
    p += __shfl_xor_sync(0xffffffffu, p, 2);
    p += __shfl_xor_sync(0xffffffffu, p, 4);
    p += __shfl_xor_sync(0xffffffffu, p, 8);
    if (sub == 0) out[edge] = p;
}

// ---------------- launch ----------------------------------------------------
extern "C" void kernel_launch(void* const* d_in, const int* in_sizes, int n_in,
                              void* d_out, int out_size) {
    const float* x    = (const float*)d_in[0];
    const int*   ei   = (const int*)d_in[1];
    const int*   pos  = (const int*)d_in[2];
    const int*   neg  = (const int*)d_in[3];
    const float* W1   = (const float*)d_in[4];
    const float* as1  = (const float*)d_in[5];
    const float* ad1  = (const float*)d_in[6];
    const float* b1   = (const float*)d_in[7];
    const float* W2   = (const float*)d_in[8];
    const float* as2  = (const float*)d_in[9];
    const float* ad2  = (const float*)d_in[10];
    const float* b2   = (const float*)d_in[11];
    float* out = (float*)d_out;

    const int TB = 256;
    const int E4 = (E2 + 3) / 4;
    const int SCAN_SMEM = NN * (int)sizeof(int);   // 200 KB dynamic smem
    cudaFuncSetAttribute(scan_kernel, cudaFuncAttributeMaxDynamicSharedMemorySize,
                         SCAN_SMEM);

    // CSR build (g_deg zeroed at load / by previous run's scan)
    count_deg<<<(E4 + TB - 1) / TB, TB>>>(ei);
    scan_kernel<<<1, 1024, SCAN_SMEM>>>();
    scatter_kernel<<<(E4 + TB - 1) / TB, TB>>>(ei);
    // layer 1 (GEMM + att fused)
    gemm_att<128, 1><<<(NN + 63) / 64, TB>>>(x, W1, as1, ad1);
    agg1_kernel<<<(NN * 32 + TB - 1) / TB, TB>>>(b1);
    // layer 2
    gemm_att<64, 2><<<(NN + 63) / 64, TB>>>(nullptr, W2, as2, ad2);
    agg2_kernel<<<(NN * 32 + TB - 1) / TB, TB>>>(b2);
    // logits (16 threads per test edge)
    logits_kernel<<<(ETOT * 16 + TB - 1) / TB, TB>>>(pos, neg, out);
}